// round 12
// baseline (speedup 1.0000x reference)
#include <cuda_runtime.h>
#include <cstdint>

// ---------------- problem constants ----------------
#define E_EXPERTS 128
#define MFEAT     2048            // GEMM K
#define NFEAT     1408            // GEMM N
#define S_TOK     16384
#define TILE_M    128
#define TILE_N    128
#define KC        32              // K floats per chunk
#define NCHUNK    (MFEAT / KC)    // 64
#define NTN       (NFEAT / TILE_N)// 11
#define MAXTILES  256
#define GRID_CTAS (MAXTILES * NTN)
#define STAGES    3
#define NTHREADS  256

#define A_STRIDE  36              // floats/row: 32 data + 4 pad; 144B rows (16B-mult)
#define B_STRIDE  136             // floats/row: 128 data + 8 pad; conflict-free frag LDS
#define A_FLOATS  (TILE_M * A_STRIDE)       // 4608
#define B_FLOATS  (KC * B_STRIDE)           // 4352
#define STAGE_FLOATS (A_FLOATS + B_FLOATS)  // 8960
#define STAGE_BYTES  (STAGE_FLOATS * 4)     // 35840
#define SMEM_DYN     (STAGES * STAGE_BYTES) // 107520 -> 2 CTAs/SM (215KB <= 228KB)

// ---------------- scheduler output ----------------
__device__ int g_ntiles;
__device__ int g_te[MAXTILES];
__device__ int g_tr0[MAXTILES];
__device__ int g_tlim[MAXTILES];

// ---------------- helpers ----------------
__device__ __forceinline__ uint32_t smem_u32(const void* p) {
    uint32_t a;
    asm("{ .reg .u64 t; cvta.to.shared.u64 t, %1; cvt.u32.u64 %0, t; }" : "=r"(a) : "l"(p));
    return a;
}

// cp.async 16B with zero-fill when pred==0 (src-size operand form)
__device__ __forceinline__ void cp16(uint32_t dst, const void* src, int pred) {
    asm volatile(
        "{\n\t.reg .pred p;\n\t.reg .b32 s;\n\t"
        "setp.ne.u32 p, %2, 0;\n\t"
        "selp.b32 s, 16, 0, p;\n\t"
        "cp.async.cg.shared.global [%0], [%1], 16, s;\n\t}"
        :: "r"(dst), "l"(src), "r"(pred));
}
#define CP_COMMIT() asm volatile("cp.async.commit_group;" ::: "memory")
#define CP_WAIT2()  asm volatile("cp.async.wait_group 2;" ::: "memory")

__device__ __forceinline__ void ldsm_x4(uint32_t& r0, uint32_t& r1, uint32_t& r2, uint32_t& r3,
                                        uint32_t addr) {
    asm volatile("ldmatrix.sync.aligned.m8n8.x4.shared.b16 {%0,%1,%2,%3}, [%4];"
                 : "=r"(r0), "=r"(r1), "=r"(r2), "=r"(r3) : "r"(addr));
}

__device__ __forceinline__ void mma_m16n8k8(float* d,
        uint32_t a0, uint32_t a1, uint32_t a2, uint32_t a3,
        uint32_t b0, uint32_t b1) {
    asm volatile(
        "mma.sync.aligned.m16n8k8.row.col.f32.tf32.tf32.f32 "
        "{%0,%1,%2,%3}, {%4,%5,%6,%7}, {%8,%9}, {%0,%1,%2,%3};"
        : "+f"(d[0]), "+f"(d[1]), "+f"(d[2]), "+f"(d[3])
        : "r"(a0), "r"(a1), "r"(a2), "r"(a3), "r"(b0), "r"(b1));
}

// ---------------- scheduler ----------------
__global__ void sched_kernel(const int* __restrict__ bs) {
    if (threadIdx.x == 0) {
        int off = 0, nt = 0;
        for (int e = 0; e < E_EXPERTS; e++) {
            int b = bs[e];
            for (int r = 0; r < b; r += TILE_M) {
                g_te[nt] = e; g_tr0[nt] = off + r; g_tlim[nt] = off + b; nt++;
            }
            off += b;
        }
        g_ntiles = nt;
    }
}

// ---------------- chunk issue: gmem -> smem via cp.async ----------------
// A: 128 rows x 8 x16B = 1024 copies; B: 32 rows x 32 x16B = 1024 copies.
// 2048 copies / 256 threads = 8 each (4 A + 4 B), fully coalesced.
__device__ __forceinline__ void issue_chunk(int c, uint32_t stA, uint32_t stB,
        const float* __restrict__ x, const float* __restrict__ wb,
        int r0, int tid) {
#pragma unroll
    for (int j = 0; j < 4; j++) {
        int task = j * 256 + tid;
        int m = task >> 3, f = task & 7;
        int gr = r0 + m;
        int ok = gr < S_TOK;
        int grc = ok ? gr : (S_TOK - 1);
        cp16(stA + (uint32_t)(m * (A_STRIDE * 4) + f * 16),
             x + (size_t)grc * MFEAT + c * KC + f * 4, ok);
    }
#pragma unroll
    for (int j = 0; j < 4; j++) {
        int task = j * 256 + tid;
        int k = task >> 5, t = task & 31;
        cp16(stB + (uint32_t)(k * (B_STRIDE * 4) + t * 16),
             wb + (size_t)(c * KC + k) * NFEAT + t * 4, 1);
    }
}

// ---------------- main grouped-GEMM kernel ----------------
// 256 threads, 8 warps (2x4), warp tile 64x32, 3-stage cp.async pipeline.
__global__ __launch_bounds__(NTHREADS, 2)
void gg_kernel(const float* __restrict__ x, const float* __restrict__ w, float* __restrict__ out) {
    int job = blockIdx.x;
    int tm = job / NTN;
    if (tm >= g_ntiles) return;
    int n0   = (job - tm * NTN) * TILE_N;
    int e    = g_te[tm];
    int r0   = g_tr0[tm];
    int rlim = g_tlim[tm];
    const float* wb = w + (size_t)e * ((size_t)MFEAT * NFEAT) + n0;

    extern __shared__ __align__(16) float smem[];
    uint32_t smem_b = smem_u32(smem);

    int tid  = threadIdx.x;
    int lane = tid & 31;
    int wid  = tid >> 5;
    int m0w  = (wid & 1) * 64;     // warp m-offset: 0 / 64
    int n0w  = (wid >> 1) * 32;    // warp n-offset: 0 / 32 / 64 / 96

    int lr = lane >> 2;            // 0..7
    int lc = lane & 3;             // 0..3
    // ldmatrix x4 lane mapping: groups of 8 lanes address the 4 8x8 tiles
    int lsub = lane >> 3;
    int r8   = lane & 7;
    int mrow = (lsub & 1) * 8 + r8;      // row within 16-row frag
    int kh   = (lsub >> 1) * 4;          // k-half (0 or 4)

    float acc[4][4][4];
#pragma unroll
    for (int i = 0; i < 4; i++)
#pragma unroll
        for (int j = 0; j < 4; j++)
#pragma unroll
            for (int q = 0; q < 4; q++) acc[i][j][q] = 0.f;

    // prologue: fill 3 stages
#pragma unroll
    for (int s = 0; s < STAGES; s++) {
        uint32_t st = smem_b + (uint32_t)s * STAGE_BYTES;
        issue_chunk(s, st, st + A_FLOATS * 4, x, wb, r0, tid);
        CP_COMMIT();
    }

    int stage = 0;
    for (int c = 0; c < NCHUNK; c++) {
        CP_WAIT2();
        __syncthreads();

        uint32_t stA = smem_b + (uint32_t)stage * STAGE_BYTES;
        const float* Bs = smem + (size_t)stage * STAGE_FLOATS + A_FLOATS;
        uint32_t aBase = stA + (uint32_t)((m0w + mrow) * (A_STRIDE * 4) + kh * 4);

#pragma unroll
        for (int s = 0; s < 4; s++) {   // 4 k-steps of 8
            uint32_t af[4][4];
#pragma unroll
            for (int mf = 0; mf < 4; mf++)
                ldsm_x4(af[mf][0], af[mf][1], af[mf][2], af[mf][3],
                        aBase + (uint32_t)(mf * 16 * (A_STRIDE * 4) + s * 32));
            uint32_t bf[4][2];
            const float* bp0 = Bs + (size_t)(s * 8 + lc) * B_STRIDE + n0w + lr;
#pragma unroll
            for (int nf = 0; nf < 4; nf++) {
                bf[nf][0] = __float_as_uint(bp0[nf * 8]);
                bf[nf][1] = __float_as_uint(bp0[4 * B_STRIDE + nf * 8]);
            }
#pragma unroll
            for (int mf = 0; mf < 4; mf++)
#pragma unroll
                for (int nf = 0; nf < 4; nf++)
                    mma_m16n8k8(acc[mf][nf],
                                af[mf][0], af[mf][1], af[mf][2], af[mf][3],
                                bf[nf][0], bf[nf][1]);
        }

        __syncthreads();
        int cn = c + STAGES;
        if (cn < NCHUNK) {
            uint32_t st = smem_b + (uint32_t)stage * STAGE_BYTES;
            issue_chunk(cn, st, st + A_FLOATS * 4, x, wb, r0, tid);
        }
        CP_COMMIT();
        stage = (stage + 1 == STAGES) ? 0 : stage + 1;
    }

    // ---------------- epilogue ----------------
#pragma unroll
    for (int mf = 0; mf < 4; mf++) {
        int r_lo = r0 + m0w + mf * 16 + lr;
#pragma unroll
        for (int h = 0; h < 2; h++) {
            int gr = r_lo + h * 8;
            if (gr < rlim) {
                float* orow = out + (size_t)gr * NFEAT + n0 + n0w + 2 * lc;
#pragma unroll
                for (int nf = 0; nf < 4; nf++) {
                    float2 v;
                    v.x = acc[mf][nf][h * 2 + 0];
                    v.y = acc[mf][nf][h * 2 + 1];
                    *(float2*)(orow + nf * 8) = v;
                }
            }
        }
    }
}

// ---------------- launch ----------------
extern "C" void kernel_launch(void* const* d_in, const int* in_sizes, int n_in,
                              void* d_out, int out_size) {
    const float* x  = (const float*)d_in[0];
    const float* w  = (const float*)d_in[1];
    const int*   bs = (const int*)d_in[2];
    float* out = (float*)d_out;

    cudaFuncSetAttribute(gg_kernel, cudaFuncAttributeMaxDynamicSharedMemorySize, SMEM_DYN);
    sched_kernel<<<1, 32>>>(bs);
    gg_kernel<<<GRID_CTAS, NTHREADS, SMEM_DYN>>>(x, w, out);
}

// round 13
// speedup vs baseline: 1.0371x; 1.0371x over previous
#include <cuda_runtime.h>
#include <cstdint>

// ---------------- problem constants ----------------
#define E_EXPERTS 128
#define MFEAT     2048            // GEMM K
#define NFEAT     1408            // GEMM N
#define S_TOK     16384
#define TILE_M    128
#define TILE_N    128
#define KC        32              // K floats per chunk
#define NCHUNK    (MFEAT / KC)    // 64
#define NTN       (NFEAT / TILE_N)// 11
#define MAXTILES  256
#define GRID_CTAS (MAXTILES * NTN)
#define STAGES    3

#define A_STRIDE  36              // floats/row: 32 data + 4 pad; 144B rows (16B-mult)
#define B_STRIDE  136             // floats/row: 128 data + 8 pad; conflict-free frag LDS
#define A_FLOATS  (TILE_M * A_STRIDE)       // 4608
#define B_FLOATS  (KC * B_STRIDE)           // 4352
#define STAGE_FLOATS (A_FLOATS + B_FLOATS)  // 8960
#define STAGE_BYTES  (STAGE_FLOATS * 4)     // 35840
#define SMEM_DYN     (STAGES * STAGE_BYTES) // 107520 -> 2 CTAs/SM (215KB <= 228KB)

// ---------------- scheduler output ----------------
__device__ int g_ntiles;
__device__ int g_te[MAXTILES];
__device__ int g_tr0[MAXTILES];
__device__ int g_tlim[MAXTILES];

// ---------------- helpers ----------------
__device__ __forceinline__ uint32_t smem_u32(const void* p) {
    uint32_t a;
    asm("{ .reg .u64 t; cvta.to.shared.u64 t, %1; cvt.u32.u64 %0, t; }" : "=r"(a) : "l"(p));
    return a;
}

// cp.async 16B with zero-fill when pred==0 (src-size operand form)
__device__ __forceinline__ void cp16(uint32_t dst, const void* src, int pred) {
    asm volatile(
        "{\n\t.reg .pred p;\n\t.reg .b32 s;\n\t"
        "setp.ne.u32 p, %2, 0;\n\t"
        "selp.b32 s, 16, 0, p;\n\t"
        "cp.async.cg.shared.global [%0], [%1], 16, s;\n\t}"
        :: "r"(dst), "l"(src), "r"(pred));
}
#define CP_COMMIT() asm volatile("cp.async.commit_group;" ::: "memory")
#define CP_WAIT1()  asm volatile("cp.async.wait_group 1;" ::: "memory")

__device__ __forceinline__ void ldsm_x4(uint32_t& r0, uint32_t& r1, uint32_t& r2, uint32_t& r3,
                                        uint32_t addr) {
    asm volatile("ldmatrix.sync.aligned.m8n8.x4.shared.b16 {%0,%1,%2,%3}, [%4];"
                 : "=r"(r0), "=r"(r1), "=r"(r2), "=r"(r3) : "r"(addr));
}

__device__ __forceinline__ void mma_m16n8k8(float* d,
        uint32_t a0, uint32_t a1, uint32_t a2, uint32_t a3,
        uint32_t b0, uint32_t b1) {
    asm volatile(
        "mma.sync.aligned.m16n8k8.row.col.f32.tf32.tf32.f32 "
        "{%0,%1,%2,%3}, {%4,%5,%6,%7}, {%8,%9}, {%0,%1,%2,%3};"
        : "+f"(d[0]), "+f"(d[1]), "+f"(d[2]), "+f"(d[3])
        : "r"(a0), "r"(a1), "r"(a2), "r"(a3), "r"(b0), "r"(b1));
}

// ---------------- scheduler ----------------
__global__ void sched_kernel(const int* __restrict__ bs) {
    if (threadIdx.x == 0) {
        int off = 0, nt = 0;
        for (int e = 0; e < E_EXPERTS; e++) {
            int b = bs[e];
            for (int r = 0; r < b; r += TILE_M) {
                g_te[nt] = e; g_tr0[nt] = off + r; g_tlim[nt] = off + b; nt++;
            }
            off += b;
        }
        g_ntiles = nt;
    }
}

// ---------------- chunk issue: gmem -> smem via cp.async ----------------
// A: 128 rows x 8 x16B = 1024 copies; B: 32 rows x 32 x16B = 1024 copies.
// 2048 copies / 128 threads = 16 each (8 A + 8 B), fully coalesced.
__device__ __forceinline__ void issue_chunk(int c, uint32_t stA, uint32_t stB,
        const float* __restrict__ x, const float* __restrict__ wb,
        int r0, int tid) {
#pragma unroll
    for (int j = 0; j < 8; j++) {
        int task = j * 128 + tid;
        int m = task >> 3, f = task & 7;
        int gr = r0 + m;
        int ok = gr < S_TOK;
        int grc = ok ? gr : (S_TOK - 1);
        cp16(stA + (uint32_t)(m * (A_STRIDE * 4) + f * 16),
             x + (size_t)grc * MFEAT + c * KC + f * 4, ok);
    }
#pragma unroll
    for (int j = 0; j < 8; j++) {
        int task = j * 128 + tid;
        int k = task >> 5, t = task & 31;
        cp16(stB + (uint32_t)(k * (B_STRIDE * 4) + t * 16),
             wb + (size_t)(c * KC + k) * NFEAT + t * 4, 1);
    }
}

// ---------------- main grouped-GEMM kernel ----------------
// 128 threads, 4 warps (2x2), warp tile 64x64, single-sync 3-stage pipeline:
//   iter c: wait(chunk c) -> sync -> issue chunk c+2 into stage freed last iter
//           -> compute chunk c.  ONE barrier per chunk.
__global__ __launch_bounds__(128, 2)
void gg_kernel(const float* __restrict__ x, const float* __restrict__ w, float* __restrict__ out) {
    int job = blockIdx.x;
    int tm = job / NTN;
    if (tm >= g_ntiles) return;
    int n0   = (job - tm * NTN) * TILE_N;
    int e    = g_te[tm];
    int r0   = g_tr0[tm];
    int rlim = g_tlim[tm];
    const float* wb = w + (size_t)e * ((size_t)MFEAT * NFEAT) + n0;

    extern __shared__ __align__(16) float smem[];
    uint32_t smem_b = smem_u32(smem);

    int tid  = threadIdx.x;
    int lane = tid & 31;
    int wid  = tid >> 5;
    int m0w  = (wid & 1) * 64;
    int n0w  = (wid >> 1) * 64;

    int lr = lane >> 2;            // 0..7
    int lc = lane & 3;             // 0..3
    int lsub = lane >> 3;
    int r8   = lane & 7;
    int mrow = (lsub & 1) * 8 + r8;      // row within 16-row frag
    int kh   = (lsub >> 1) * 4;          // k-half (0 or 4)

    float acc[4][8][4];
#pragma unroll
    for (int i = 0; i < 4; i++)
#pragma unroll
        for (int j = 0; j < 8; j++)
#pragma unroll
            for (int q = 0; q < 4; q++) acc[i][j][q] = 0.f;

    // prologue: fill STAGES-1 = 2 stages
#pragma unroll
    for (int s = 0; s < STAGES - 1; s++) {
        uint32_t st = smem_b + (uint32_t)s * STAGE_BYTES;
        issue_chunk(s, st, st + A_FLOATS * 4, x, wb, r0, tid);
        CP_COMMIT();
    }

    for (int c = 0; c < NCHUNK; c++) {
        CP_WAIT1();               // chunk c landed (newest pending group may be c+1)
        __syncthreads();          // chunk c visible to all; stage (c-1)%3 fully consumed

        // issue chunk c+2 into stage (c+2)%3 == (c-1)%3 (freed by the sync above)
        int cn = c + STAGES - 1;
        if (cn < NCHUNK) {
            uint32_t st = smem_b + (uint32_t)(cn % STAGES) * STAGE_BYTES;
            issue_chunk(cn, st, st + A_FLOATS * 4, x, wb, r0, tid);
        }
        CP_COMMIT();              // commit (possibly empty) keeps group accounting fixed

        int stage = c % STAGES;
        uint32_t stA = smem_b + (uint32_t)stage * STAGE_BYTES;
        const float* Bs = smem + (size_t)stage * STAGE_FLOATS + A_FLOATS;
        uint32_t aBase = stA + (uint32_t)((m0w + mrow) * (A_STRIDE * 4) + kh * 4);

#pragma unroll
        for (int s = 0; s < 4; s++) {   // 4 k-steps of 8
            uint32_t af[4][4];
#pragma unroll
            for (int mf = 0; mf < 4; mf++)
                ldsm_x4(af[mf][0], af[mf][1], af[mf][2], af[mf][3],
                        aBase + (uint32_t)(mf * 16 * (A_STRIDE * 4) + s * 32));
            uint32_t bf[8][2];
            const float* bp0 = Bs + (size_t)(s * 8 + lc) * B_STRIDE + n0w + lr;
#pragma unroll
            for (int nf = 0; nf < 8; nf++) {
                bf[nf][0] = __float_as_uint(bp0[nf * 8]);
                bf[nf][1] = __float_as_uint(bp0[4 * B_STRIDE + nf * 8]);
            }
#pragma unroll
            for (int mf = 0; mf < 4; mf++)
#pragma unroll
                for (int nf = 0; nf < 8; nf++)
                    mma_m16n8k8(acc[mf][nf],
                                af[mf][0], af[mf][1], af[mf][2], af[mf][3],
                                bf[nf][0], bf[nf][1]);
        }
    }

    // ---------------- epilogue ----------------
#pragma unroll
    for (int mf = 0; mf < 4; mf++) {
        int r_lo = r0 + m0w + mf * 16 + lr;
#pragma unroll
        for (int h = 0; h < 2; h++) {
            int gr = r_lo + h * 8;
            if (gr < rlim) {
                float* orow = out + (size_t)gr * NFEAT + n0 + n0w + 2 * lc;
#pragma unroll
                for (int nf = 0; nf < 8; nf++) {
                    float2 v;
                    v.x = acc[mf][nf][h * 2 + 0];
                    v.y = acc[mf][nf][h * 2 + 1];
                    *(float2*)(orow + nf * 8) = v;
                }
            }
        }
    }
}

// ---------------- launch ----------------
extern "C" void kernel_launch(void* const* d_in, const int* in_sizes, int n_in,
                              void* d_out, int out_size) {
    const float* x  = (const float*)d_in[0];
    const float* w  = (const float*)d_in[1];
    const int*   bs = (const int*)d_in[2];
    float* out = (float*)d_out;

    cudaFuncSetAttribute(gg_kernel, cudaFuncAttributeMaxDynamicSharedMemorySize, SMEM_DYN);
    sched_kernel<<<1, 32>>>(bs);
    gg_kernel<<<GRID_CTAS, 128, SMEM_DYN>>>(x, w, out);
}

// round 14
// speedup vs baseline: 1.1279x; 1.0876x over previous
#include <cuda_runtime.h>
#include <cstdint>

// ---------------- problem constants ----------------
#define E_EXPERTS 128
#define MFEAT     2048            // GEMM K
#define NFEAT     1408            // GEMM N
#define S_TOK     16384
#define TILE_M    128
#define TILE_N    128
#define KC        32              // K floats per chunk
#define NCHUNK    (MFEAT / KC)    // 64
#define NTN       (NFEAT / TILE_N)// 11
#define MAXTILES  256
#define GRID_CTAS (MAXTILES * NTN)
#define STAGES    3

#define A_STRIDE  36              // floats/row: 32 data + 4 pad; 144B rows (16B-mult)
#define B_STRIDE  136             // floats/row: 128 data + 8 pad; conflict-free frag LDS
#define A_FLOATS  (TILE_M * A_STRIDE)       // 4608
#define B_FLOATS  (KC * B_STRIDE)           // 4352
#define STAGE_FLOATS (A_FLOATS + B_FLOATS)  // 8960
#define STAGE_BYTES  (STAGE_FLOATS * 4)     // 35840
#define SMEM_DYN     (STAGES * STAGE_BYTES) // 107520 -> 2 CTAs/SM (215KB <= 228KB)

// ---------------- scheduler output ----------------
__device__ int g_ntiles;
__device__ int g_te[MAXTILES];
__device__ int g_tr0[MAXTILES];
__device__ int g_tlim[MAXTILES];

// ---------------- helpers ----------------
__device__ __forceinline__ uint32_t smem_u32(const void* p) {
    uint32_t a;
    asm("{ .reg .u64 t; cvta.to.shared.u64 t, %1; cvt.u32.u64 %0, t; }" : "=r"(a) : "l"(p));
    return a;
}

// cp.async 16B with zero-fill when pred==0 (src-size operand form)
__device__ __forceinline__ void cp16(uint32_t dst, const void* src, int pred) {
    asm volatile(
        "{\n\t.reg .pred p;\n\t.reg .b32 s;\n\t"
        "setp.ne.u32 p, %2, 0;\n\t"
        "selp.b32 s, 16, 0, p;\n\t"
        "cp.async.cg.shared.global [%0], [%1], 16, s;\n\t}"
        :: "r"(dst), "l"(src), "r"(pred));
}
#define CP_COMMIT() asm volatile("cp.async.commit_group;" ::: "memory")
#define CP_WAIT1()  asm volatile("cp.async.wait_group 1;" ::: "memory")

__device__ __forceinline__ void ldsm_x4(uint32_t& r0, uint32_t& r1, uint32_t& r2, uint32_t& r3,
                                        uint32_t addr) {
    asm volatile("ldmatrix.sync.aligned.m8n8.x4.shared.b16 {%0,%1,%2,%3}, [%4];"
                 : "=r"(r0), "=r"(r1), "=r"(r2), "=r"(r3) : "r"(addr));
}

__device__ __forceinline__ void mma_m16n8k8(float* d,
        uint32_t a0, uint32_t a1, uint32_t a2, uint32_t a3,
        uint32_t b0, uint32_t b1) {
    asm volatile(
        "mma.sync.aligned.m16n8k8.row.col.f32.tf32.tf32.f32 "
        "{%0,%1,%2,%3}, {%4,%5,%6,%7}, {%8,%9}, {%0,%1,%2,%3};"
        : "+f"(d[0]), "+f"(d[1]), "+f"(d[2]), "+f"(d[3])
        : "r"(a0), "r"(a1), "r"(a2), "r"(a3), "r"(b0), "r"(b1));
}

// ---------------- scheduler ----------------
__global__ void sched_kernel(const int* __restrict__ bs) {
    if (threadIdx.x == 0) {
        int off = 0, nt = 0;
        for (int e = 0; e < E_EXPERTS; e++) {
            int b = bs[e];
            for (int r = 0; r < b; r += TILE_M) {
                g_te[nt] = e; g_tr0[nt] = off + r; g_tlim[nt] = off + b; nt++;
            }
            off += b;
        }
        g_ntiles = nt;
    }
}

// ---------------- chunk issue: gmem -> smem via cp.async ----------------
// A: 128 rows x 8 x16B = 1024 copies; B: 32 rows x 32 x16B = 1024 copies.
// 2048 copies / 128 threads = 16 each (8 A + 8 B), fully coalesced.
__device__ __forceinline__ void issue_chunk(int c, uint32_t stA, uint32_t stB,
        const float* __restrict__ x, const float* __restrict__ wb,
        int r0, int tid) {
#pragma unroll
    for (int j = 0; j < 8; j++) {
        int task = j * 128 + tid;
        int m = task >> 3, f = task & 7;
        int gr = r0 + m;
        int ok = gr < S_TOK;
        int grc = ok ? gr : (S_TOK - 1);
        cp16(stA + (uint32_t)(m * (A_STRIDE * 4) + f * 16),
             x + (size_t)grc * MFEAT + c * KC + f * 4, ok);
    }
#pragma unroll
    for (int j = 0; j < 8; j++) {
        int task = j * 128 + tid;
        int k = task >> 5, t = task & 31;
        cp16(stB + (uint32_t)(k * (B_STRIDE * 4) + t * 16),
             wb + (size_t)(c * KC + k) * NFEAT + t * 4, 1);
    }
}

// ---------------- main grouped-GEMM kernel ----------------
// 128 threads, 4 warps (2x2), warp tile 64x64, 3-stage cp.async pipeline.
// ONE barrier per chunk, load issue AFTER compute (in the pre-barrier shadow):
//   iter c: wait(chunk c) -> sync -> compute chunk c (stage c%3)
//           -> issue chunk c+2 into stage (c+2)%3 == (c-1)%3 -> commit.
// Safety of the single sync: every thread issues c+2 only after its compute c,
// which is after sync(c), which all threads reached only after finishing
// compute c-1 — so stage (c-1)%3 is certainly fully consumed before overwrite.
__global__ __launch_bounds__(128, 2)
void gg_kernel(const float* __restrict__ x, const float* __restrict__ w, float* __restrict__ out) {
    int job = blockIdx.x;
    int tm = job / NTN;
    if (tm >= g_ntiles) return;
    int n0   = (job - tm * NTN) * TILE_N;
    int e    = g_te[tm];
    int r0   = g_tr0[tm];
    int rlim = g_tlim[tm];
    const float* wb = w + (size_t)e * ((size_t)MFEAT * NFEAT) + n0;

    extern __shared__ __align__(16) float smem[];
    uint32_t smem_b = smem_u32(smem);

    int tid  = threadIdx.x;
    int lane = tid & 31;
    int wid  = tid >> 5;
    int m0w  = (wid & 1) * 64;
    int n0w  = (wid >> 1) * 64;

    int lr = lane >> 2;            // 0..7
    int lc = lane & 3;             // 0..3
    int lsub = lane >> 3;
    int r8   = lane & 7;
    int mrow = (lsub & 1) * 8 + r8;      // row within 16-row frag
    int kh   = (lsub >> 1) * 4;          // k-half (0 or 4)

    float acc[4][8][4];
#pragma unroll
    for (int i = 0; i < 4; i++)
#pragma unroll
        for (int j = 0; j < 8; j++)
#pragma unroll
            for (int q = 0; q < 4; q++) acc[i][j][q] = 0.f;

    // prologue: fill STAGES-1 = 2 stages
#pragma unroll
    for (int s = 0; s < STAGES - 1; s++) {
        uint32_t st = smem_b + (uint32_t)s * STAGE_BYTES;
        issue_chunk(s, st, st + A_FLOATS * 4, x, wb, r0, tid);
        CP_COMMIT();
    }

    for (int c = 0; c < NCHUNK; c++) {
        CP_WAIT1();               // chunk c landed (chunk c+1 may stay pending)
        __syncthreads();          // c visible to all; everyone finished compute c-1

        int stage = c % STAGES;
        uint32_t stA = smem_b + (uint32_t)stage * STAGE_BYTES;
        const float* Bs = smem + (size_t)stage * STAGE_FLOATS + A_FLOATS;
        uint32_t aBase = stA + (uint32_t)((m0w + mrow) * (A_STRIDE * 4) + kh * 4);

#pragma unroll
        for (int s = 0; s < 4; s++) {   // 4 k-steps of 8
            uint32_t af[4][4];
#pragma unroll
            for (int mf = 0; mf < 4; mf++)
                ldsm_x4(af[mf][0], af[mf][1], af[mf][2], af[mf][3],
                        aBase + (uint32_t)(mf * 16 * (A_STRIDE * 4) + s * 32));
            uint32_t bf[8][2];
            const float* bp0 = Bs + (size_t)(s * 8 + lc) * B_STRIDE + n0w + lr;
#pragma unroll
            for (int nf = 0; nf < 8; nf++) {
                bf[nf][0] = __float_as_uint(bp0[nf * 8]);
                bf[nf][1] = __float_as_uint(bp0[4 * B_STRIDE + nf * 8]);
            }
#pragma unroll
            for (int mf = 0; mf < 4; mf++)
#pragma unroll
                for (int nf = 0; nf < 8; nf++)
                    mma_m16n8k8(acc[mf][nf],
                                af[mf][0], af[mf][1], af[mf][2], af[mf][3],
                                bf[nf][0], bf[nf][1]);
        }

        // issue chunk c+2 into the stage freed by compute c-1 (pre-barrier shadow)
        int cn = c + STAGES - 1;
        if (cn < NCHUNK) {
            uint32_t st = smem_b + (uint32_t)(cn % STAGES) * STAGE_BYTES;
            issue_chunk(cn, st, st + A_FLOATS * 4, x, wb, r0, tid);
        }
        CP_COMMIT();              // commit (possibly empty) keeps group accounting fixed
    }

    // ---------------- epilogue ----------------
#pragma unroll
    for (int mf = 0; mf < 4; mf++) {
        int r_lo = r0 + m0w + mf * 16 + lr;
#pragma unroll
        for (int h = 0; h < 2; h++) {
            int gr = r_lo + h * 8;
            if (gr < rlim) {
                float* orow = out + (size_t)gr * NFEAT + n0 + n0w + 2 * lc;
#pragma unroll
                for (int nf = 0; nf < 8; nf++) {
                    float2 v;
                    v.x = acc[mf][nf][h * 2 + 0];
                    v.y = acc[mf][nf][h * 2 + 1];
                    *(float2*)(orow + nf * 8) = v;
                }
            }
        }
    }
}

// ---------------- launch ----------------
extern "C" void kernel_launch(void* const* d_in, const int* in_sizes, int n_in,
                              void* d_out, int out_size) {
    const float* x  = (const float*)d_in[0];
    const float* w  = (const float*)d_in[1];
    const int*   bs = (const int*)d_in[2];
    float* out = (float*)d_out;

    cudaFuncSetAttribute(gg_kernel, cudaFuncAttributeMaxDynamicSharedMemorySize, SMEM_DYN);
    sched_kernel<<<1, 32>>>(bs);
    gg_kernel<<<GRID_CTAS, 128, SMEM_DYN>>>(x, w, out);
}

// round 15
// speedup vs baseline: 1.3375x; 1.1858x over previous
#include <cuda_runtime.h>
#include <cstdint>

// ---------------- problem constants ----------------
#define E_EXPERTS 128
#define MFEAT     2048            // GEMM K
#define NFEAT     1408            // GEMM N
#define S_TOK     16384
#define TILE_M    128
#define TILE_N    128
#define KC        32              // K floats per chunk
#define NCHUNK    (MFEAT / KC)    // 64
#define NTN       (NFEAT / TILE_N)// 11
#define MAXTILES  320
#define GRID_CTAS (MAXTILES * NTN)
#define STAGES    3

#define A_STRIDE  36              // floats/row: 32 data + 4 pad; 144B rows (16B-mult)
#define B_STRIDE  136             // floats/row: 128 data + 8 pad; conflict-free frag LDS
#define A_FLOATS  (TILE_M * A_STRIDE)       // 4608
#define B_FLOATS  (KC * B_STRIDE)           // 4352
#define STAGE_FLOATS (A_FLOATS + B_FLOATS)  // 8960
#define STAGE_BYTES  (STAGE_FLOATS * 4)     // 35840
#define SMEM_DYN     (STAGES * STAGE_BYTES) // 107520 -> 2 CTAs/SM (215KB <= 228KB)

// ---------------- scheduler output ----------------
__device__ int g_ntiles;
__device__ int g_te[MAXTILES];
__device__ int g_tr0[MAXTILES];
__device__ int g_tlim[MAXTILES];
__device__ int g_tq[MAXTILES];      // tile height in 32-row quarters (1..4)

// ---------------- helpers ----------------
__device__ __forceinline__ uint32_t smem_u32(const void* p) {
    uint32_t a;
    asm("{ .reg .u64 t; cvta.to.shared.u64 t, %1; cvt.u32.u64 %0, t; }" : "=r"(a) : "l"(p));
    return a;
}

// cp.async 16B with zero-fill when pred==0 (src-size operand form)
__device__ __forceinline__ void cp16(uint32_t dst, const void* src, int pred) {
    asm volatile(
        "{\n\t.reg .pred p;\n\t.reg .b32 s;\n\t"
        "setp.ne.u32 p, %2, 0;\n\t"
        "selp.b32 s, 16, 0, p;\n\t"
        "cp.async.cg.shared.global [%0], [%1], 16, s;\n\t}"
        :: "r"(dst), "l"(src), "r"(pred));
}
#define CP_COMMIT() asm volatile("cp.async.commit_group;" ::: "memory")
#define CP_WAIT1()  asm volatile("cp.async.wait_group 1;" ::: "memory")

__device__ __forceinline__ void ldsm_x4(uint32_t& r0, uint32_t& r1, uint32_t& r2, uint32_t& r3,
                                        uint32_t addr) {
    asm volatile("ldmatrix.sync.aligned.m8n8.x4.shared.b16 {%0,%1,%2,%3}, [%4];"
                 : "=r"(r0), "=r"(r1), "=r"(r2), "=r"(r3) : "r"(addr));
}

__device__ __forceinline__ void mma_m16n8k8(float* d,
        uint32_t a0, uint32_t a1, uint32_t a2, uint32_t a3,
        uint32_t b0, uint32_t b1) {
    asm volatile(
        "mma.sync.aligned.m16n8k8.row.col.f32.tf32.tf32.f32 "
        "{%0,%1,%2,%3}, {%4,%5,%6,%7}, {%8,%9}, {%0,%1,%2,%3};"
        : "+f"(d[0]), "+f"(d[1]), "+f"(d[2]), "+f"(d[3])
        : "r"(a0), "r"(a1), "r"(a2), "r"(a3), "r"(b0), "r"(b1));
}

// ---------------- scheduler ----------------
__global__ void sched_kernel(const int* __restrict__ bs) {
    if (threadIdx.x == 0) {
        int off = 0, nt = 0;
        for (int e = 0; e < E_EXPERTS; e++) {
            int b = bs[e];
            int r = 0;
            for (; r + TILE_M <= b; r += TILE_M) {   // full 128-row tiles
                g_te[nt] = e; g_tr0[nt] = off + r; g_tlim[nt] = off + b; g_tq[nt] = 4; nt++;
            }
            int rem = b - r;
            if (rem > 0) {                            // remainder tile, 32-row granularity
                g_te[nt] = e; g_tr0[nt] = off + r; g_tlim[nt] = off + b;
                g_tq[nt] = (rem + 31) >> 5; nt++;
            }
            off += b;
        }
        g_ntiles = nt;
    }
}

// ---------------- chunk issue: gmem -> smem via cp.async ----------------
// A: 128 rows x 8 x16B; rows >= arows become zfill (no gmem traffic).
// B: 32 k-rows x 32 x16B. 2048 copies / 128 threads = 16 each, coalesced.
__device__ __forceinline__ void issue_chunk(int c, uint32_t stA, uint32_t stB,
        const float* __restrict__ x, const float* __restrict__ wb,
        int r0, int arows, int tid) {
#pragma unroll
    for (int j = 0; j < 8; j++) {
        int task = j * 128 + tid;
        int m = task >> 3, f = task & 7;
        int gr = r0 + m;
        int ok = (m < arows) && (gr < S_TOK);
        int grc = ok ? gr : 0;
        cp16(stA + (uint32_t)(m * (A_STRIDE * 4) + f * 16),
             x + (size_t)grc * MFEAT + c * KC + f * 4, ok);
    }
#pragma unroll
    for (int j = 0; j < 8; j++) {
        int task = j * 128 + tid;
        int k = task >> 5, t = task & 31;
        cp16(stB + (uint32_t)(k * (B_STRIDE * 4) + t * 16),
             wb + (size_t)(c * KC + k) * NFEAT + t * 4, 1);
    }
}

// ---------------- one chunk of compute, MFC 16-row frags (1..4) ----------------
template<int MFC>
__device__ __forceinline__ void compute_chunk(float acc[4][8][4],
        uint32_t aBase, const float* Bs, int lc, int lr, int n0w) {
#pragma unroll
    for (int s = 0; s < 4; s++) {   // 4 k-steps of 8
        uint32_t af[MFC][4];
#pragma unroll
        for (int mf = 0; mf < MFC; mf++)
            ldsm_x4(af[mf][0], af[mf][1], af[mf][2], af[mf][3],
                    aBase + (uint32_t)(mf * 16 * (A_STRIDE * 4) + s * 32));
        uint32_t bf[8][2];
        const float* bp0 = Bs + (size_t)(s * 8 + lc) * B_STRIDE + n0w + lr;
#pragma unroll
        for (int nf = 0; nf < 8; nf++) {
            bf[nf][0] = __float_as_uint(bp0[nf * 8]);
            bf[nf][1] = __float_as_uint(bp0[4 * B_STRIDE + nf * 8]);
        }
#pragma unroll
        for (int mf = 0; mf < MFC; mf++)
#pragma unroll
            for (int nf = 0; nf < 8; nf++)
                mma_m16n8k8(acc[mf][nf],
                            af[mf][0], af[mf][1], af[mf][2], af[mf][3],
                            bf[nf][0], bf[nf][1]);
    }
}

// ---------------- main grouped-GEMM kernel ----------------
// 128 threads, 4 warps (2x2), warp tile 64x64, 3-stage cp.async pipeline,
// ONE barrier per chunk, issue-after-compute.  Tiles have variable height
// (32-row quarters); warps skip HMMA frags above the tile height.
__global__ __launch_bounds__(128, 2)
void gg_kernel(const float* __restrict__ x, const float* __restrict__ w, float* __restrict__ out) {
    int job = blockIdx.x;
    int tm = job / NTN;
    if (tm >= g_ntiles) return;
    int n0   = (job - tm * NTN) * TILE_N;
    int e    = g_te[tm];
    int r0   = g_tr0[tm];
    int rlim = g_tlim[tm];
    int mq   = g_tq[tm];                 // 1..4 quarters
    int arows = mq * 32;
    const float* wb = w + (size_t)e * ((size_t)MFEAT * NFEAT) + n0;

    extern __shared__ __align__(16) float smem[];
    uint32_t smem_b = smem_u32(smem);

    int tid  = threadIdx.x;
    int lane = tid & 31;
    int wid  = tid >> 5;
    int m0w  = (wid & 1) * 64;
    int n0w  = (wid >> 1) * 64;

    // number of 16-row frags this warp computes: clamp(2*mq - 4*(wid&1), 0, 4)
    int mf_cnt = 2 * mq - 4 * (wid & 1);
    mf_cnt = mf_cnt < 0 ? 0 : (mf_cnt > 4 ? 4 : mf_cnt);

    int lr = lane >> 2;            // 0..7
    int lc = lane & 3;             // 0..3
    int lsub = lane >> 3;
    int r8   = lane & 7;
    int mrow = (lsub & 1) * 8 + r8;      // row within 16-row frag
    int kh   = (lsub >> 1) * 4;          // k-half (0 or 4)

    float acc[4][8][4];
#pragma unroll
    for (int i = 0; i < 4; i++)
#pragma unroll
        for (int j = 0; j < 8; j++)
#pragma unroll
            for (int q = 0; q < 4; q++) acc[i][j][q] = 0.f;

    // prologue: fill STAGES-1 = 2 stages
#pragma unroll
    for (int s = 0; s < STAGES - 1; s++) {
        uint32_t st = smem_b + (uint32_t)s * STAGE_BYTES;
        issue_chunk(s, st, st + A_FLOATS * 4, x, wb, r0, arows, tid);
        CP_COMMIT();
    }

    for (int c = 0; c < NCHUNK; c++) {
        CP_WAIT1();               // chunk c landed (chunk c+1 may stay pending)
        __syncthreads();          // c visible; everyone finished compute c-1

        int stage = c % STAGES;
        uint32_t stA = smem_b + (uint32_t)stage * STAGE_BYTES;
        const float* Bs = smem + (size_t)stage * STAGE_FLOATS + A_FLOATS;
        uint32_t aBase = stA + (uint32_t)((m0w + mrow) * (A_STRIDE * 4) + kh * 4);

        // warp-uniform dispatch; no barriers inside the branches
        switch (mf_cnt) {
            case 4: compute_chunk<4>(acc, aBase, Bs, lc, lr, n0w); break;
            case 3: compute_chunk<3>(acc, aBase, Bs, lc, lr, n0w); break;
            case 2: compute_chunk<2>(acc, aBase, Bs, lc, lr, n0w); break;
            case 1: compute_chunk<1>(acc, aBase, Bs, lc, lr, n0w); break;
            default: break;
        }

        // issue chunk c+2 into the stage freed by compute c-1 (pre-barrier shadow)
        int cn = c + STAGES - 1;
        if (cn < NCHUNK) {
            uint32_t st = smem_b + (uint32_t)(cn % STAGES) * STAGE_BYTES;
            issue_chunk(cn, st, st + A_FLOATS * 4, x, wb, r0, arows, tid);
        }
        CP_COMMIT();              // commit (possibly empty) keeps group accounting fixed
    }

    // ---------------- epilogue ----------------
#pragma unroll
    for (int mf = 0; mf < 4; mf++) {
        int r_lo = r0 + m0w + mf * 16 + lr;
#pragma unroll
        for (int h = 0; h < 2; h++) {
            int gr = r_lo + h * 8;
            if (gr < rlim) {
                float* orow = out + (size_t)gr * NFEAT + n0 + n0w + 2 * lc;
#pragma unroll
                for (int nf = 0; nf < 8; nf++) {
                    float2 v;
                    v.x = acc[mf][nf][h * 2 + 0];
                    v.y = acc[mf][nf][h * 2 + 1];
                    *(float2*)(orow + nf * 8) = v;
                }
            }
        }
    }
}

// ---------------- launch ----------------
extern "C" void kernel_launch(void* const* d_in, const int* in_sizes, int n_in,
                              void* d_out, int out_size) {
    const float* x  = (const float*)d_in[0];
    const float* w  = (const float*)d_in[1];
    const int*   bs = (const int*)d_in[2];
    float* out = (float*)d_out;

    cudaFuncSetAttribute(gg_kernel, cudaFuncAttributeMaxDynamicSharedMemorySize, SMEM_DYN);
    sched_kernel<<<1, 32>>>(bs);
    gg_kernel<<<GRID_CTAS, 128, SMEM_DYN>>>(x, w, out);
}